// round 6
// baseline (speedup 1.0000x reference)
#include <cuda_runtime.h>

// ---------------------------------------------------------------------------
// HybridSAGEClassifier on GB300 — R6.
//   vs R5: GEMM retiled 64x128 (4x8 microtile, ~75 regs) with
//   __launch_bounds__(256,3) -> 3 CTAs/SM instead of 1. Occupancy was the
//   binding constraint (occ=12.5%, fma=42%, regs=131 in R5 profile).
// edge_index is int32 on the wire.
// ---------------------------------------------------------------------------

static constexpr int N_NODES = 100000;
static constexpr int N_EDGES = 1200000;
static constexpr int SCHUNK  = 1024;
static constexpr int SNB     = (N_NODES + SCHUNK - 1) / SCHUNK;   // 98

// -------- device-global scratch --------------------------------------------
__device__ __align__(128) int   g_deg[N_NODES];
__device__ __align__(128) int   g_rowptr[N_NODES + 1];
__device__ __align__(128) int   g_cursor[N_NODES];
__device__ __align__(128) int   g_col[N_EDGES];
__device__ __align__(128) float g_inv[N_NODES];
__device__ __align__(128) int   g_bsum[SNB];
__device__ __align__(128) int   g_boff[SNB];
__device__ __align__(128) float g_bufA[(size_t)N_NODES * 64];
__device__ __align__(128) float g_buf0[(size_t)N_NODES * 64];
__device__ __align__(128) float g_buf1[(size_t)N_NODES * 64];
__device__ __align__(128) float g_sum[64];
__device__ __align__(128) float g_sumsq[64];
__device__ __align__(128) float g_scale[64];
__device__ __align__(128) float g_shift[64];

__device__ __forceinline__ float* getbuf(int s) {
    return (s == 0) ? g_bufA : (s == 1) ? g_buf0 : g_buf1;
}
__device__ __forceinline__ int clampN(int v) {
    return (v < 0) ? 0 : (v >= N_NODES ? N_NODES - 1 : v);
}

// -------- CSR build --------------------------------------------------------
__global__ void k_zero_deg() {
    int i = blockIdx.x * blockDim.x + threadIdx.x;
    if (i < N_NODES) g_deg[i] = 0;
}
__global__ void k_zero_stats() {
    int i = threadIdx.x;
    if (i < 64) { g_sum[i] = 0.f; g_sumsq[i] = 0.f; }
}
__global__ void k_hist(const int* __restrict__ ei) {
    int e = blockIdx.x * blockDim.x + threadIdx.x;
    if (e < N_EDGES) atomicAdd(&g_deg[clampN(ei[N_EDGES + e])], 1);
}

// 3-phase exclusive prefix scan of g_deg -> g_rowptr/g_cursor/g_inv
__global__ __launch_bounds__(256) void k_scan1() {
    __shared__ int sh[256];
    int b = blockIdx.x, t = threadIdx.x;
    int base = b * SCHUNK + t * 4;
    int s = 0;
#pragma unroll
    for (int i = 0; i < 4; i++) {
        int idx = base + i;
        if (idx < N_NODES) s += g_deg[idx];
    }
    sh[t] = s;
    __syncthreads();
    for (int off = 128; off > 0; off >>= 1) {
        if (t < off) sh[t] += sh[t + off];
        __syncthreads();
    }
    if (t == 0) g_bsum[b] = sh[0];
}
__global__ __launch_bounds__(128) void k_scan2() {
    __shared__ int sh[128];
    int t = threadIdx.x;
    int v = (t < SNB) ? g_bsum[t] : 0;
    sh[t] = v;
    __syncthreads();
    for (int off = 1; off < 128; off <<= 1) {
        int a = (t >= off) ? sh[t - off] : 0;
        __syncthreads();
        sh[t] += a;
        __syncthreads();
    }
    if (t < SNB) g_boff[t] = sh[t] - v;   // exclusive
}
__global__ __launch_bounds__(256) void k_scan3() {
    __shared__ int sh[256];
    int b = blockIdx.x, t = threadIdx.x;
    int base = b * SCHUNK + t * 4;
    int local[4];
    int s = 0;
#pragma unroll
    for (int i = 0; i < 4; i++) {
        int idx = base + i;
        local[i] = (idx < N_NODES) ? g_deg[idx] : 0;
        s += local[i];
    }
    sh[t] = s;
    __syncthreads();
    for (int off = 1; off < 256; off <<= 1) {
        int a = (t >= off) ? sh[t - off] : 0;
        __syncthreads();
        sh[t] += a;
        __syncthreads();
    }
    int run = g_boff[b] + sh[t] - s;
#pragma unroll
    for (int i = 0; i < 4; i++) {
        int idx = base + i;
        if (idx < N_NODES) {
            g_rowptr[idx] = run;
            g_cursor[idx] = run;
            int d = local[i];
            g_inv[idx] = 1.0f / (float)(d > 0 ? d : 1);
            run += d;
        }
    }
    if (b == 0 && t == 0) g_rowptr[N_NODES] = N_EDGES;
}
__global__ void k_scatter(const int* __restrict__ ei) {
    int e = blockIdx.x * blockDim.x + threadIdx.x;
    if (e < N_EDGES) {
        int d = clampN(ei[N_EDGES + e]);
        int p = atomicAdd(&g_cursor[d], 1);
        g_col[p] = clampN(ei[e]);
    }
}

// -------- merged GEMM (64 rows x 128 cols per CTA, 3 CTAs/SM) ---------------
//   A[r, 0:64]  = BNx(X)[r,:] @ Wl          -> getbuf(oselA)
//   H[r, 0:64]  = BNx(X)[r,:] @ Wr + bias   -> getbuf(oselH)
// BNx = identity (BN=false) or relu(x*g_scale + g_shift) per channel.
// 256 threads, 4x8 microtile (32 acc regs), reg-double-buffered k-tiles.
template <int D, bool BN>
__global__ __launch_bounds__(256, 3) void k_gemm2(const float* __restrict__ Xext,
                                                  int xsel,
                                                  const float* __restrict__ Wl,
                                                  const float* __restrict__ Wr,
                                                  const float* __restrict__ bias,
                                                  int oselA, int oselH) {
    const float* __restrict__ X = (xsel < 0) ? Xext : getbuf(xsel);
    float* __restrict__ OA = getbuf(oselA);
    float* __restrict__ OH = getbuf(oselH);

    __shared__ float Xs[16][68];     // [k][row], stride 68 -> 16B-aligned rows
    __shared__ float Ws[16][128];    // [k][col] (0..63 = Wl, 64..127 = Wr)
    __shared__ float ssc[64], ssh[64];

    const int tid  = threadIdx.x;
    const int row0 = blockIdx.x * 64;
    const int ty4  = (tid >> 4) * 4;   // rows ty4..ty4+3
    const int tx8  = (tid & 15) * 8;   // cols tx8..tx8+7

    if (BN) {
        if (tid < 64) { ssc[tid] = g_scale[tid]; ssh[tid] = g_shift[tid]; }
        __syncthreads();
    }

    // X tile loads: 64 rows x 16 k = 256 float4, one per thread
    const int xr_row = tid >> 2;       // 0..63
    const int xr_j   = tid & 3;        // float4 within the 16-k span
    // W tile loads: 16 k x 128 cols = 512 float4, two per thread
    const int wk0 = tid >> 4,          wc0 = tid & 15;          // first 256
    const int wk1 = (tid + 256) >> 4,  wc1 = tid & 15;          // second 256 (wk+16? no:)
    // NOTE: idx = tid + 256 -> wk = idx >> 5, wc = idx & 31 mapping instead:
    // use generic mapping below.

    float acc[4][8];
#pragma unroll
    for (int i = 0; i < 4; i++)
#pragma unroll
        for (int j = 0; j < 8; j++) acc[i][j] = 0.f;

    const int T = D / 16;
    float4 xr, wr[2];

    const int wA_k = (tid * 2) >> 5, wA_c = (tid * 2) & 31;
    const int wB_k = (tid * 2 + 1) >> 5, wB_c = (tid * 2 + 1) & 31;

    auto loadX = [&](int k0, float4& r) {
        int rr = row0 + xr_row; if (rr >= N_NODES) rr = N_NODES - 1;
        r = *(const float4*)(X + (size_t)rr * D + k0 + xr_j * 4);
    };
    auto loadW = [&](int k0, float4* r) {
        r[0] = (wA_c < 16) ? *(const float4*)(Wl + (size_t)(k0 + wA_k) * 64 + wA_c * 4)
                           : *(const float4*)(Wr + (size_t)(k0 + wA_k) * 64 + (wA_c - 16) * 4);
        r[1] = (wB_c < 16) ? *(const float4*)(Wl + (size_t)(k0 + wB_k) * 64 + wB_c * 4)
                           : *(const float4*)(Wr + (size_t)(k0 + wB_k) * 64 + (wB_c - 16) * 4);
    };
    auto bnv = [&](float v, int ch) -> float {
        if (BN) return fmaxf(fmaf(v, ssc[ch], ssh[ch]), 0.f);
        return v;
    };
    auto storeX = [&](int k0, const float4& r) {
        int c = k0 + xr_j * 4;
        Xs[xr_j * 4 + 0][xr_row] = bnv(r.x, (c + 0) & 63);
        Xs[xr_j * 4 + 1][xr_row] = bnv(r.y, (c + 1) & 63);
        Xs[xr_j * 4 + 2][xr_row] = bnv(r.z, (c + 2) & 63);
        Xs[xr_j * 4 + 3][xr_row] = bnv(r.w, (c + 3) & 63);
    };
    auto storeW = [&](const float4* r) {
        int c0 = (wA_c < 16) ? wA_c * 4 : 64 + (wA_c - 16) * 4;
        int c1 = (wB_c < 16) ? wB_c * 4 : 64 + (wB_c - 16) * 4;
        *(float4*)&Ws[wA_k][c0] = r[0];
        *(float4*)&Ws[wB_k][c1] = r[1];
    };

    loadX(0, xr);
    loadW(0, wr);
    int k0 = 0;
    for (int t = 0; t < T; t++) {
        storeX(k0, xr);
        storeW(wr);
        __syncthreads();
        if (t + 1 < T) { loadX(k0 + 16, xr); loadW(k0 + 16, wr); }

#pragma unroll
        for (int kk = 0; kk < 16; kk++) {
            float av[4], wv[8];
            *(float4*)&av[0] = *(const float4*)&Xs[kk][ty4];
            *(float4*)&wv[0] = *(const float4*)&Ws[kk][tx8];
            *(float4*)&wv[4] = *(const float4*)&Ws[kk][tx8 + 4];
#pragma unroll
            for (int i = 0; i < 4; i++)
#pragma unroll
                for (int j = 0; j < 8; j++)
                    acc[i][j] = fmaf(av[i], wv[j], acc[i][j]);
        }
        __syncthreads();
        k0 += 16;
    }

    const bool isH = (tx8 >= 64);
    float* __restrict__ O = isH ? OH : OA;
    const int oc = isH ? (tx8 - 64) : tx8;
    float bv[8];
#pragma unroll
    for (int j = 0; j < 8; j++) bv[j] = isH ? bias[oc + j] : 0.f;

#pragma unroll
    for (int i = 0; i < 4; i++) {
        int r = row0 + ty4 + i;
        if (r < N_NODES) {
            float4 o0 = make_float4(acc[i][0] + bv[0], acc[i][1] + bv[1],
                                    acc[i][2] + bv[2], acc[i][3] + bv[3]);
            float4 o1 = make_float4(acc[i][4] + bv[4], acc[i][5] + bv[5],
                                    acc[i][6] + bv[6], acc[i][7] + bv[7]);
            *(float4*)(O + (size_t)r * 64 + oc)     = o0;
            *(float4*)(O + (size_t)r * 64 + oc + 4) = o1;
        }
    }
}

// -------- SpMM + BN statistics ---------------------------------------------
__global__ __launch_bounds__(256) void k_spmm_stats(int asel, int hsel) {
    const float* __restrict__ A = getbuf(asel);
    float* __restrict__ H = getbuf(hsel);
    __shared__ float ssum[64], ssq[64];
    if (threadIdx.x < 64) { ssum[threadIdx.x] = 0.f; ssq[threadIdx.x] = 0.f; }
    __syncthreads();

    int gw   = (blockIdx.x * blockDim.x + threadIdx.x) >> 5;
    int lane = threadIdx.x & 31;
    if (gw < N_NODES) {
        int beg = g_rowptr[gw];
        int end = g_rowptr[gw + 1];
        float2 acc = make_float2(0.f, 0.f);
        for (int e0 = beg; e0 < end; e0 += 32) {
            int c = (e0 + lane < end) ? g_col[e0 + lane] : 0;
            int n = end - e0;
            if (n > 32) n = 32;
#pragma unroll 8
            for (int i = 0; i < n; i++) {
                int s = __shfl_sync(0xffffffffu, c, i);
                float2 v = *(const float2*)(A + (size_t)s * 64 + lane * 2);
                acc.x += v.x;
                acc.y += v.y;
            }
        }
        float inv = g_inv[gw];
        float2* hp = (float2*)(H + (size_t)gw * 64 + lane * 2);
        float2 h = *hp;
        h.x = fmaf(acc.x, inv, h.x);
        h.y = fmaf(acc.y, inv, h.y);
        *hp = h;
        atomicAdd(&ssum[lane * 2],     h.x);
        atomicAdd(&ssum[lane * 2 + 1], h.y);
        atomicAdd(&ssq[lane * 2],      h.x * h.x);
        atomicAdd(&ssq[lane * 2 + 1],  h.y * h.y);
    }
    __syncthreads();
    if (threadIdx.x < 64) {
        atomicAdd(&g_sum[threadIdx.x],   ssum[threadIdx.x]);
        atomicAdd(&g_sumsq[threadIdx.x], ssq[threadIdx.x]);
    }
}

// -------- BN finalize (re-zeroes accumulators for next layer) ---------------
__global__ void k_finalize(const float* __restrict__ g, const float* __restrict__ be) {
    int c = threadIdx.x;
    if (c < 64) {
        float mu  = g_sum[c] / (float)N_NODES;
        float var = g_sumsq[c] / (float)N_NODES - mu * mu;
        float sc  = g[c] * rsqrtf(var + 1e-5f);
        g_scale[c] = sc;
        g_shift[c] = be[c] - mu * sc;
        g_sum[c]   = 0.f;
        g_sumsq[c] = 0.f;
    }
}

// -------- fusion MLP (applies layer-3 BN+ReLU on the fly) -------------------
__global__ __launch_bounds__(256) void k_fusion(int hsel,
                                                const float* __restrict__ xgb,
                                                const float* __restrict__ Wf1,
                                                const float* __restrict__ bf1,
                                                const float* __restrict__ Wf2,
                                                const float* __restrict__ bf2,
                                                float* __restrict__ out) {
    const float* __restrict__ H = getbuf(hsel);
    __shared__ float sW[65 * 64];
    __shared__ float sb1[64], sW2[64], ssc[64], ssh[64];
    __shared__ float sb2;
    for (int i = threadIdx.x; i < 65 * 64; i += 256) sW[i] = Wf1[i];
    if (threadIdx.x < 64) {
        sb1[threadIdx.x] = bf1[threadIdx.x];
        sW2[threadIdx.x] = Wf2[threadIdx.x];
        ssc[threadIdx.x] = g_scale[threadIdx.x];
        ssh[threadIdx.x] = g_shift[threadIdx.x];
    }
    if (threadIdx.x == 0) sb2 = bf2[0];
    __syncthreads();

    int node = blockIdx.x * 256 + threadIdx.x;
    if (node >= N_NODES) return;

    const float4* hp = (const float4*)(H + (size_t)node * 64);
    float4 acc[16];
#pragma unroll
    for (int jg = 0; jg < 16; jg++) acc[jg] = ((const float4*)sb1)[jg];

    for (int kc = 0; kc < 8; kc++) {
        float  hv[8];
        float4 h0 = hp[kc * 2];
        float4 h1 = hp[kc * 2 + 1];
        hv[0] = h0.x; hv[1] = h0.y; hv[2] = h0.z; hv[3] = h0.w;
        hv[4] = h1.x; hv[5] = h1.y; hv[6] = h1.z; hv[7] = h1.w;
#pragma unroll
        for (int kk = 0; kk < 8; kk++) {
            int ch = kc * 8 + kk;
            float x = fmaxf(fmaf(hv[kk], ssc[ch], ssh[ch]), 0.f);
            const float* wr = &sW[ch * 64];
#pragma unroll
            for (int jg = 0; jg < 16; jg++) {
                float4 w = *(const float4*)&wr[jg * 4];
                acc[jg].x = fmaf(x, w.x, acc[jg].x);
                acc[jg].y = fmaf(x, w.y, acc[jg].y);
                acc[jg].z = fmaf(x, w.z, acc[jg].z);
                acc[jg].w = fmaf(x, w.w, acc[jg].w);
            }
        }
    }

    float xg    = xgb[node];
    float logit = sb2;
#pragma unroll
    for (int jg = 0; jg < 16; jg++) {
        float4 w = *(const float4*)&sW[64 * 64 + jg * 4];
        float4 a = acc[jg];
        a.x = fmaxf(fmaf(xg, w.x, a.x), 0.f);
        a.y = fmaxf(fmaf(xg, w.y, a.y), 0.f);
        a.z = fmaxf(fmaf(xg, w.z, a.z), 0.f);
        a.w = fmaxf(fmaf(xg, w.w, a.w), 0.f);
        float4 v2 = *(const float4*)&sW2[jg * 4];
        logit += a.x * v2.x + a.y * v2.y + a.z * v2.z + a.w * v2.w;
    }
    out[node] = logit;
}

// ---------------------------------------------------------------------------
extern "C" void kernel_launch(void* const* d_in, const int* in_sizes, int n_in,
                              void* d_out, int out_size) {
    const float* x    = (const float*)d_in[0];
    const int*   ei   = (const int*)d_in[1];
    const float* xgb  = (const float*)d_in[2];
    const float* W1l  = (const float*)d_in[3];
    const float* b1   = (const float*)d_in[4];
    const float* W1r  = (const float*)d_in[5];
    const float* g1   = (const float*)d_in[6];
    const float* be1  = (const float*)d_in[7];
    const float* W2l  = (const float*)d_in[8];
    const float* b2   = (const float*)d_in[9];
    const float* W2r  = (const float*)d_in[10];
    const float* g2   = (const float*)d_in[11];
    const float* be2  = (const float*)d_in[12];
    const float* W3l  = (const float*)d_in[13];
    const float* b3   = (const float*)d_in[14];
    const float* W3r  = (const float*)d_in[15];
    const float* g3   = (const float*)d_in[16];
    const float* be3  = (const float*)d_in[17];
    const float* Wf1  = (const float*)d_in[18];
    const float* bf1  = (const float*)d_in[19];
    const float* Wf2  = (const float*)d_in[20];
    const float* bf2  = (const float*)d_in[21];
    float*       out  = (float*)d_out;

    const int EB = (N_EDGES + 255) / 256;
    const int GB = (N_NODES + 63) / 64;
    const int SB = (N_NODES * 32 + 255) / 256;
    const int FB = (N_NODES + 255) / 256;

    // 1-3: CSR hist + stat init
    k_zero_deg<<<(N_NODES + 255) / 256, 256>>>();
    k_hist<<<EB, 256>>>(ei);
    k_zero_stats<<<1, 64>>>();

    // 4: layer-1 merged GEMM (no CSR dependency) — profiled slot
    k_gemm2<128, false><<<GB, 256>>>(x, -1, W1l, W1r, b1, 0, 2);

    // 5-8: finish CSR
    k_scan1<<<SNB, 256>>>();
    k_scan2<<<1, 128>>>();
    k_scan3<<<SNB, 256>>>();
    k_scatter<<<EB, 256>>>(ei);

    // layer 1 aggregate + BN
    k_spmm_stats<<<SB, 256>>>(0, 2);
    k_finalize<<<1, 64>>>(g1, be1);

    // layer 2
    k_gemm2<64, true><<<GB, 256>>>(nullptr, 2, W2l, W2r, b2, 0, 1);
    k_spmm_stats<<<SB, 256>>>(0, 1);
    k_finalize<<<1, 64>>>(g2, be2);

    // layer 3
    k_gemm2<64, true><<<GB, 256>>>(nullptr, 1, W3l, W3r, b3, 0, 2);
    k_spmm_stats<<<SB, 256>>>(0, 2);
    k_finalize<<<1, 64>>>(g3, be3);

    // fusion (applies BN3 on the fly)
    k_fusion<<<FB, 256>>>(2, xgb, Wf1, bf1, Wf2, bf2, out);
}

// round 11
// speedup vs baseline: 1.2226x; 1.2226x over previous
#include <cuda_runtime.h>

// ---------------------------------------------------------------------------
// HybridSAGEClassifier on GB300 — R8.
//   = R7 with the SpMM deadlock fixed: the 16-lane-group shfl now uses a
//   group-local mask (0xFFFF << (tid & 16)). R7's full-warp mask deadlocked
//   when the two half-warps (different nodes, different degrees) diverged.
// edge_index is int32 on the wire.
// ---------------------------------------------------------------------------

static constexpr int N_NODES = 100000;
static constexpr int N_EDGES = 1200000;
static constexpr int SCHUNK  = 1024;
static constexpr int SNB     = (N_NODES + SCHUNK - 1) / SCHUNK;   // 98

// -------- device-global scratch --------------------------------------------
__device__ __align__(128) int   g_deg[N_NODES];
__device__ __align__(128) int   g_rowptr[N_NODES + 1];
__device__ __align__(128) int   g_cursor[N_NODES];
__device__ __align__(128) int   g_col[N_EDGES];
__device__ __align__(128) float g_inv[N_NODES];
__device__ __align__(128) int   g_bsum[SNB];
__device__ __align__(128) int   g_boff[SNB];
__device__ __align__(128) float g_bufA[(size_t)N_NODES * 64];
__device__ __align__(128) float g_buf0[(size_t)N_NODES * 64];
__device__ __align__(128) float g_buf1[(size_t)N_NODES * 64];
__device__ __align__(128) float g_sum[64];
__device__ __align__(128) float g_sumsq[64];
__device__ __align__(128) float g_scale[64];
__device__ __align__(128) float g_shift[64];

__device__ __forceinline__ float* getbuf(int s) {
    return (s == 0) ? g_bufA : (s == 1) ? g_buf0 : g_buf1;
}
__device__ __forceinline__ int clampN(int v) {
    return (v < 0) ? 0 : (v >= N_NODES ? N_NODES - 1 : v);
}

// -------- CSR build --------------------------------------------------------
__global__ void k_zero_deg() {
    int i = blockIdx.x * blockDim.x + threadIdx.x;
    if (i < N_NODES) g_deg[i] = 0;
}
__global__ void k_zero_stats() {
    int i = threadIdx.x;
    if (i < 64) { g_sum[i] = 0.f; g_sumsq[i] = 0.f; }
}
__global__ void k_hist(const int* __restrict__ ei) {
    int e = blockIdx.x * blockDim.x + threadIdx.x;
    if (e < N_EDGES) atomicAdd(&g_deg[clampN(ei[N_EDGES + e])], 1);
}

__global__ __launch_bounds__(256) void k_scan1() {
    __shared__ int sh[256];
    int b = blockIdx.x, t = threadIdx.x;
    int base = b * SCHUNK + t * 4;
    int s = 0;
#pragma unroll
    for (int i = 0; i < 4; i++) {
        int idx = base + i;
        if (idx < N_NODES) s += g_deg[idx];
    }
    sh[t] = s;
    __syncthreads();
    for (int off = 128; off > 0; off >>= 1) {
        if (t < off) sh[t] += sh[t + off];
        __syncthreads();
    }
    if (t == 0) g_bsum[b] = sh[0];
}
__global__ __launch_bounds__(128) void k_scan2() {
    __shared__ int sh[128];
    int t = threadIdx.x;
    int v = (t < SNB) ? g_bsum[t] : 0;
    sh[t] = v;
    __syncthreads();
    for (int off = 1; off < 128; off <<= 1) {
        int a = (t >= off) ? sh[t - off] : 0;
        __syncthreads();
        sh[t] += a;
        __syncthreads();
    }
    if (t < SNB) g_boff[t] = sh[t] - v;
}
__global__ __launch_bounds__(256) void k_scan3() {
    __shared__ int sh[256];
    int b = blockIdx.x, t = threadIdx.x;
    int base = b * SCHUNK + t * 4;
    int local[4];
    int s = 0;
#pragma unroll
    for (int i = 0; i < 4; i++) {
        int idx = base + i;
        local[i] = (idx < N_NODES) ? g_deg[idx] : 0;
        s += local[i];
    }
    sh[t] = s;
    __syncthreads();
    for (int off = 1; off < 256; off <<= 1) {
        int a = (t >= off) ? sh[t - off] : 0;
        __syncthreads();
        sh[t] += a;
        __syncthreads();
    }
    int run = g_boff[b] + sh[t] - s;
#pragma unroll
    for (int i = 0; i < 4; i++) {
        int idx = base + i;
        if (idx < N_NODES) {
            g_rowptr[idx] = run;
            g_cursor[idx] = run;
            int d = local[i];
            g_inv[idx] = 1.0f / (float)(d > 0 ? d : 1);
            run += d;
        }
    }
    if (b == 0 && t == 0) g_rowptr[N_NODES] = N_EDGES;
}
__global__ void k_scatter(const int* __restrict__ ei) {
    int e = blockIdx.x * blockDim.x + threadIdx.x;
    if (e < N_EDGES) {
        int d = clampN(ei[N_EDGES + e]);
        int p = atomicAdd(&g_cursor[d], 1);
        g_col[p] = clampN(ei[e]);
    }
}

// -------- merged GEMM (pure, no BN) ----------------------------------------
//   A[r, 0:64]  = X[r,:] @ Wl          -> getbuf(oselA)
//   H[r, 0:64]  = X[r,:] @ Wr + bias   -> getbuf(oselH)
// 128x128 tile, 256 threads, 8x8 microtile, reg-double-buffered, 2 CTAs/SM.
template <int D>
__global__ __launch_bounds__(256, 2) void k_gemm2(const float* __restrict__ Xext,
                                                  int xsel,
                                                  const float* __restrict__ Wl,
                                                  const float* __restrict__ Wr,
                                                  const float* __restrict__ bias,
                                                  int oselA, int oselH) {
    const float* __restrict__ X = (xsel < 0) ? Xext : getbuf(xsel);
    float* __restrict__ OA = getbuf(oselA);
    float* __restrict__ OH = getbuf(oselH);

    __shared__ float Xs[16][132];
    __shared__ float Ws[16][128];

    const int tid  = threadIdx.x;
    const int row0 = blockIdx.x * 128;
    const int ty8  = (tid >> 4) * 8;
    const int tx8  = (tid & 15) * 8;

    const int xr_r0 = (tid * 2) >> 2;
    const int xr_j0 = (tid * 2) & 3;
    const int xr_r1 = (tid * 2 + 1) >> 2;
    const int xr_j1 = (tid * 2 + 1) & 3;
    const int wk0 = (tid * 2) >> 5, wc0 = (tid * 2) & 31;
    const int wk1 = (tid * 2 + 1) >> 5, wc1 = (tid * 2 + 1) & 31;

    float acc[8][8];
#pragma unroll
    for (int i = 0; i < 8; i++)
#pragma unroll
        for (int j = 0; j < 8; j++) acc[i][j] = 0.f;

    const int T = D / 16;
    float4 xr[2], wr[2];

    auto loadX = [&](int k0, float4* r) {
        int rr0 = row0 + xr_r0; if (rr0 >= N_NODES) rr0 = N_NODES - 1;
        int rr1 = row0 + xr_r1; if (rr1 >= N_NODES) rr1 = N_NODES - 1;
        r[0] = *(const float4*)(X + (size_t)rr0 * D + k0 + xr_j0 * 4);
        r[1] = *(const float4*)(X + (size_t)rr1 * D + k0 + xr_j1 * 4);
    };
    auto loadW = [&](int k0, float4* r) {
        r[0] = (wc0 < 16) ? *(const float4*)(Wl + (size_t)(k0 + wk0) * 64 + wc0 * 4)
                          : *(const float4*)(Wr + (size_t)(k0 + wk0) * 64 + (wc0 - 16) * 4);
        r[1] = (wc1 < 16) ? *(const float4*)(Wl + (size_t)(k0 + wk1) * 64 + wc1 * 4)
                          : *(const float4*)(Wr + (size_t)(k0 + wk1) * 64 + (wc1 - 16) * 4);
    };
    auto storeX = [&](const float4* r) {
        Xs[xr_j0 * 4 + 0][xr_r0] = r[0].x;
        Xs[xr_j0 * 4 + 1][xr_r0] = r[0].y;
        Xs[xr_j0 * 4 + 2][xr_r0] = r[0].z;
        Xs[xr_j0 * 4 + 3][xr_r0] = r[0].w;
        Xs[xr_j1 * 4 + 0][xr_r1] = r[1].x;
        Xs[xr_j1 * 4 + 1][xr_r1] = r[1].y;
        Xs[xr_j1 * 4 + 2][xr_r1] = r[1].z;
        Xs[xr_j1 * 4 + 3][xr_r1] = r[1].w;
    };
    auto storeW = [&](const float4* r) {
        int c0 = (wc0 < 16) ? wc0 * 4 : 64 + (wc0 - 16) * 4;
        int c1 = (wc1 < 16) ? wc1 * 4 : 64 + (wc1 - 16) * 4;
        *(float4*)&Ws[wk0][c0] = r[0];
        *(float4*)&Ws[wk1][c1] = r[1];
    };

    loadX(0, xr);
    loadW(0, wr);
    int k0 = 0;
    for (int t = 0; t < T; t++) {
        storeX(xr);
        storeW(wr);
        __syncthreads();
        if (t + 1 < T) { loadX(k0 + 16, xr); loadW(k0 + 16, wr); }

#pragma unroll
        for (int kk = 0; kk < 16; kk++) {
            float av[8], wv[8];
            *(float4*)&av[0] = *(const float4*)&Xs[kk][ty8];
            *(float4*)&av[4] = *(const float4*)&Xs[kk][ty8 + 4];
            *(float4*)&wv[0] = *(const float4*)&Ws[kk][tx8];
            *(float4*)&wv[4] = *(const float4*)&Ws[kk][tx8 + 4];
#pragma unroll
            for (int i = 0; i < 8; i++)
#pragma unroll
                for (int j = 0; j < 8; j++)
                    acc[i][j] = fmaf(av[i], wv[j], acc[i][j]);
        }
        __syncthreads();
        k0 += 16;
    }

    const bool isH = (tx8 >= 64);
    float* __restrict__ O = isH ? OH : OA;
    const int oc = isH ? (tx8 - 64) : tx8;
    float bv[8];
#pragma unroll
    for (int j = 0; j < 8; j++) bv[j] = isH ? bias[oc + j] : 0.f;

#pragma unroll
    for (int i = 0; i < 8; i++) {
        int r = row0 + ty8 + i;
        if (r < N_NODES) {
            float4 o0 = make_float4(acc[i][0] + bv[0], acc[i][1] + bv[1],
                                    acc[i][2] + bv[2], acc[i][3] + bv[3]);
            float4 o1 = make_float4(acc[i][4] + bv[4], acc[i][5] + bv[5],
                                    acc[i][6] + bv[6], acc[i][7] + bv[7]);
            *(float4*)(O + (size_t)r * 64 + oc)     = o0;
            *(float4*)(O + (size_t)r * 64 + oc + 4) = o1;
        }
    }
}

// -------- SpMM + BN statistics ---------------------------------------------
// 16 lanes per dst node (float4 per lane), 2 nodes per warp.
// shfl uses the GROUP-LOCAL mask: the two 16-lane groups of a warp have
// different loop trip counts, so a full-warp mask would deadlock (R7 bug).
__global__ __launch_bounds__(256) void k_spmm_stats(int asel, int hsel) {
    const float4* __restrict__ A = (const float4*)getbuf(asel);
    float* __restrict__ H = getbuf(hsel);
    __shared__ float ssum[64], ssq[64];
    if (threadIdx.x < 64) { ssum[threadIdx.x] = 0.f; ssq[threadIdx.x] = 0.f; }
    __syncthreads();

    int node = (blockIdx.x * blockDim.x + threadIdx.x) >> 4;
    int l16  = threadIdx.x & 15;
    const unsigned gmask = 0xFFFFu << (threadIdx.x & 16);   // this 16-lane group
    if (node < N_NODES) {
        int beg = g_rowptr[node];
        int end = g_rowptr[node + 1];
        float4 acc = make_float4(0.f, 0.f, 0.f, 0.f);
        for (int e0 = beg; e0 < end; e0 += 16) {
            int c = (e0 + l16 < end) ? g_col[e0 + l16] : 0;
            int n = end - e0;
            if (n > 16) n = 16;
#pragma unroll 8
            for (int i = 0; i < n; i++) {
                int s = __shfl_sync(gmask, c, i, 16);
                float4 v = A[(size_t)s * 16 + l16];
                acc.x += v.x; acc.y += v.y; acc.z += v.z; acc.w += v.w;
            }
        }
        float inv = g_inv[node];
        float4* hp = (float4*)(H + (size_t)node * 64) + l16;
        float4 h = *hp;
        h.x = fmaf(acc.x, inv, h.x);
        h.y = fmaf(acc.y, inv, h.y);
        h.z = fmaf(acc.z, inv, h.z);
        h.w = fmaf(acc.w, inv, h.w);
        *hp = h;
        atomicAdd(&ssum[l16 * 4 + 0], h.x);
        atomicAdd(&ssum[l16 * 4 + 1], h.y);
        atomicAdd(&ssum[l16 * 4 + 2], h.z);
        atomicAdd(&ssum[l16 * 4 + 3], h.w);
        atomicAdd(&ssq[l16 * 4 + 0], h.x * h.x);
        atomicAdd(&ssq[l16 * 4 + 1], h.y * h.y);
        atomicAdd(&ssq[l16 * 4 + 2], h.z * h.z);
        atomicAdd(&ssq[l16 * 4 + 3], h.w * h.w);
    }
    __syncthreads();
    if (threadIdx.x < 64) {
        atomicAdd(&g_sum[threadIdx.x],   ssum[threadIdx.x]);
        atomicAdd(&g_sumsq[threadIdx.x], ssq[threadIdx.x]);
    }
}

// -------- BN finalize (re-zeroes accumulators for next layer) ---------------
__global__ void k_finalize(const float* __restrict__ g, const float* __restrict__ be) {
    int c = threadIdx.x;
    if (c < 64) {
        float mu  = g_sum[c] / (float)N_NODES;
        float var = g_sumsq[c] / (float)N_NODES - mu * mu;
        float sc  = g[c] * rsqrtf(var + 1e-5f);
        g_scale[c] = sc;
        g_shift[c] = be[c] - mu * sc;
        g_sum[c]   = 0.f;
        g_sumsq[c] = 0.f;
    }
}

// -------- in-place BN + ReLU -----------------------------------------------
__global__ __launch_bounds__(256) void k_bnrelu(int hsel) {
    float* __restrict__ H = getbuf(hsel);
    int i = blockIdx.x * blockDim.x + threadIdx.x;   // float4 index
    if (i < N_NODES * 16) {
        float4 v = ((float4*)H)[i];
        int c = (i & 15) * 4;
        v.x = fmaxf(fmaf(v.x, g_scale[c + 0], g_shift[c + 0]), 0.f);
        v.y = fmaxf(fmaf(v.y, g_scale[c + 1], g_shift[c + 1]), 0.f);
        v.z = fmaxf(fmaf(v.z, g_scale[c + 2], g_shift[c + 2]), 0.f);
        v.w = fmaxf(fmaf(v.w, g_scale[c + 3], g_shift[c + 3]), 0.f);
        ((float4*)H)[i] = v;
    }
}

// -------- fusion MLP (applies layer-3 BN+ReLU on the fly) -------------------
__global__ __launch_bounds__(256) void k_fusion(int hsel,
                                                const float* __restrict__ xgb,
                                                const float* __restrict__ Wf1,
                                                const float* __restrict__ bf1,
                                                const float* __restrict__ Wf2,
                                                const float* __restrict__ bf2,
                                                float* __restrict__ out) {
    const float* __restrict__ H = getbuf(hsel);
    __shared__ float sW[65 * 64];
    __shared__ float sb1[64], sW2[64], ssc[64], ssh[64];
    __shared__ float sb2;
    for (int i = threadIdx.x; i < 65 * 64; i += 256) sW[i] = Wf1[i];
    if (threadIdx.x < 64) {
        sb1[threadIdx.x] = bf1[threadIdx.x];
        sW2[threadIdx.x] = Wf2[threadIdx.x];
        ssc[threadIdx.x] = g_scale[threadIdx.x];
        ssh[threadIdx.x] = g_shift[threadIdx.x];
    }
    if (threadIdx.x == 0) sb2 = bf2[0];
    __syncthreads();

    int node = blockIdx.x * 256 + threadIdx.x;
    if (node >= N_NODES) return;

    const float4* hp = (const float4*)(H + (size_t)node * 64);
    float4 acc[16];
#pragma unroll
    for (int jg = 0; jg < 16; jg++) acc[jg] = ((const float4*)sb1)[jg];

    for (int kc = 0; kc < 8; kc++) {
        float  hv[8];
        float4 h0 = hp[kc * 2];
        float4 h1 = hp[kc * 2 + 1];
        hv[0] = h0.x; hv[1] = h0.y; hv[2] = h0.z; hv[3] = h0.w;
        hv[4] = h1.x; hv[5] = h1.y; hv[6] = h1.z; hv[7] = h1.w;
#pragma unroll
        for (int kk = 0; kk < 8; kk++) {
            int ch = kc * 8 + kk;
            float x = fmaxf(fmaf(hv[kk], ssc[ch], ssh[ch]), 0.f);
            const float* wr = &sW[ch * 64];
#pragma unroll
            for (int jg = 0; jg < 16; jg++) {
                float4 w = *(const float4*)&wr[jg * 4];
                acc[jg].x = fmaf(x, w.x, acc[jg].x);
                acc[jg].y = fmaf(x, w.y, acc[jg].y);
                acc[jg].z = fmaf(x, w.z, acc[jg].z);
                acc[jg].w = fmaf(x, w.w, acc[jg].w);
            }
        }
    }

    float xg    = xgb[node];
    float logit = sb2;
#pragma unroll
    for (int jg = 0; jg < 16; jg++) {
        float4 w = *(const float4*)&sW[64 * 64 + jg * 4];
        float4 a = acc[jg];
        a.x = fmaxf(fmaf(xg, w.x, a.x), 0.f);
        a.y = fmaxf(fmaf(xg, w.y, a.y), 0.f);
        a.z = fmaxf(fmaf(xg, w.z, a.z), 0.f);
        a.w = fmaxf(fmaf(xg, w.w, a.w), 0.f);
        float4 v2 = *(const float4*)&sW2[jg * 4];
        logit += a.x * v2.x + a.y * v2.y + a.z * v2.z + a.w * v2.w;
    }
    out[node] = logit;
}

// ---------------------------------------------------------------------------
extern "C" void kernel_launch(void* const* d_in, const int* in_sizes, int n_in,
                              void* d_out, int out_size) {
    const float* x    = (const float*)d_in[0];
    const int*   ei   = (const int*)d_in[1];
    const float* xgb  = (const float*)d_in[2];
    const float* W1l  = (const float*)d_in[3];
    const float* b1   = (const float*)d_in[4];
    const float* W1r  = (const float*)d_in[5];
    const float* g1   = (const float*)d_in[6];
    const float* be1  = (const float*)d_in[7];
    const float* W2l  = (const float*)d_in[8];
    const float* b2   = (const float*)d_in[9];
    const float* W2r  = (const float*)d_in[10];
    const float* g2   = (const float*)d_in[11];
    const float* be2  = (const float*)d_in[12];
    const float* W3l  = (const float*)d_in[13];
    const float* b3   = (const float*)d_in[14];
    const float* W3r  = (const float*)d_in[15];
    const float* g3   = (const float*)d_in[16];
    const float* be3  = (const float*)d_in[17];
    const float* Wf1  = (const float*)d_in[18];
    const float* bf1  = (const float*)d_in[19];
    const float* Wf2  = (const float*)d_in[20];
    const float* bf2  = (const float*)d_in[21];
    float*       out  = (float*)d_out;

    const int EB = (N_EDGES + 255) / 256;
    const int GB = (N_NODES + 127) / 128;
    const int SB = (N_NODES * 16 + 255) / 256;
    const int VB = (N_NODES * 16 + 255) / 256;
    const int FB = (N_NODES + 255) / 256;

    // 1-3: CSR hist + stat init
    k_zero_deg<<<(N_NODES + 255) / 256, 256>>>();
    k_hist<<<EB, 256>>>(ei);
    k_zero_stats<<<1, 64>>>();

    // 4: layer-1 merged GEMM (no CSR dependency) — profiled slot
    k_gemm2<128><<<GB, 256>>>(x, -1, W1l, W1r, b1, 0, 2);

    // 5-8: finish CSR
    k_scan1<<<SNB, 256>>>();
    k_scan2<<<1, 128>>>();
    k_scan3<<<SNB, 256>>>();
    k_scatter<<<EB, 256>>>(ei);

    // layer 1 aggregate + BN (in-place)
    k_spmm_stats<<<SB, 256>>>(0, 2);
    k_finalize<<<1, 64>>>(g1, be1);
    k_bnrelu<<<VB, 256>>>(2);

    // layer 2
    k_gemm2<64><<<GB, 256>>>(nullptr, 2, W2l, W2r, b2, 0, 1);
    k_spmm_stats<<<SB, 256>>>(0, 1);
    k_finalize<<<1, 64>>>(g2, be2);
    k_bnrelu<<<VB, 256>>>(1);

    // layer 3 (BN3 applied inside fusion)
    k_gemm2<64><<<GB, 256>>>(nullptr, 1, W3l, W3r, b3, 0, 2);
    k_spmm_stats<<<SB, 256>>>(0, 2);
    k_finalize<<<1, 64>>>(g3, be3);

    // fusion
    k_fusion<<<FB, 256>>>(2, xgb, Wf1, bf1, Wf2, bf2, out);
}

// round 16
// speedup vs baseline: 1.2815x; 1.0482x over previous
#include <cuda_runtime.h>
#include <cuda_bf16.h>
#include <cstdint>

// ---------------------------------------------------------------------------
// HybridSAGEClassifier on GB300 — R15.
//   = R14 with the smem OOB fixed: Blo sits +PART after Bhi (not +2*PART).
//   GEMM via mma.sync bf16 split-3 (D = Xhi*Whi + Xhi*Wlo + Xlo*Whi).
// ---------------------------------------------------------------------------

static constexpr int N_NODES = 100000;
static constexpr int N_EDGES = 1200000;
static constexpr int SCHUNK  = 1024;
static constexpr int SNB     = (N_NODES + SCHUNK - 1) / SCHUNK;   // 98

// -------- device-global scratch --------------------------------------------
__device__ __align__(128) int   g_deg[N_NODES];
__device__ __align__(128) int   g_rowptr[N_NODES + 1];
__device__ __align__(128) int   g_cursor[N_NODES];
__device__ __align__(128) int   g_col[N_EDGES];
__device__ __align__(128) float g_inv[N_NODES];
__device__ __align__(128) int   g_bsum[SNB];
__device__ __align__(128) int   g_boff[SNB];
__device__ __align__(128) float g_bufA[(size_t)N_NODES * 64];
__device__ __align__(128) float g_buf0[(size_t)N_NODES * 64];
__device__ __align__(128) float g_buf1[(size_t)N_NODES * 64];
__device__ __align__(128) float g_sum[64];
__device__ __align__(128) float g_sumsq[64];
__device__ __align__(128) float g_scale[64];
__device__ __align__(128) float g_shift[64];
// padded bf16 W images [128][K+8] hi/lo; max 128*136*2 = 34816 bytes
__device__ __align__(128) unsigned char g_Bhi[34816];
__device__ __align__(128) unsigned char g_Blo[34816];

__device__ __forceinline__ float* getbuf(int s) {
    return (s == 0) ? g_bufA : (s == 1) ? g_buf0 : g_buf1;
}
__device__ __forceinline__ int clampN(int v) {
    return (v < 0) ? 0 : (v >= N_NODES ? N_NODES - 1 : v);
}
__device__ __forceinline__ uint32_t smem_u32(const void* p) {
    uint32_t a;
    asm("{ .reg .u64 t; cvta.to.shared.u64 t, %1; cvt.u32.u64 %0, t; }" : "=r"(a) : "l"(p));
    return a;
}

#define LDSM4(r, addr) \
    asm volatile("ldmatrix.sync.aligned.m8n8.x4.shared.b16 {%0,%1,%2,%3}, [%4];" \
                 : "=r"((r)[0]), "=r"((r)[1]), "=r"((r)[2]), "=r"((r)[3]) : "r"(addr))

#define MMA_BF16(d, a, b0, b1) \
    asm volatile("mma.sync.aligned.m16n8k16.row.col.f32.bf16.bf16.f32 " \
                 "{%0,%1,%2,%3}, {%4,%5,%6,%7}, {%8,%9}, {%0,%1,%2,%3};" \
                 : "+f"((d)[0]), "+f"((d)[1]), "+f"((d)[2]), "+f"((d)[3]) \
                 : "r"((a)[0]), "r"((a)[1]), "r"((a)[2]), "r"((a)[3]), "r"(b0), "r"(b1))

// -------- CSR build --------------------------------------------------------
__global__ void k_zero_deg() {
    int i = blockIdx.x * blockDim.x + threadIdx.x;
    if (i < N_NODES) g_deg[i] = 0;
}
__global__ void k_zero_stats() {
    int i = threadIdx.x;
    if (i < 64) { g_sum[i] = 0.f; g_sumsq[i] = 0.f; }
}
__global__ void k_hist(const int* __restrict__ ei) {
    int i = blockIdx.x * blockDim.x + threadIdx.x;
    if (i < N_EDGES / 4) {
        int4 d = *(const int4*)(ei + N_EDGES + i * 4);
        atomicAdd(&g_deg[clampN(d.x)], 1);
        atomicAdd(&g_deg[clampN(d.y)], 1);
        atomicAdd(&g_deg[clampN(d.z)], 1);
        atomicAdd(&g_deg[clampN(d.w)], 1);
    }
}
__global__ __launch_bounds__(256) void k_scan1() {
    __shared__ int sh[256];
    int b = blockIdx.x, t = threadIdx.x;
    int base = b * SCHUNK + t * 4;
    int s = 0;
#pragma unroll
    for (int i = 0; i < 4; i++) {
        int idx = base + i;
        if (idx < N_NODES) s += g_deg[idx];
    }
    sh[t] = s;
    __syncthreads();
    for (int off = 128; off > 0; off >>= 1) {
        if (t < off) sh[t] += sh[t + off];
        __syncthreads();
    }
    if (t == 0) g_bsum[b] = sh[0];
}
__global__ __launch_bounds__(128) void k_scan2() {
    __shared__ int sh[128];
    int t = threadIdx.x;
    int v = (t < SNB) ? g_bsum[t] : 0;
    sh[t] = v;
    __syncthreads();
    for (int off = 1; off < 128; off <<= 1) {
        int a = (t >= off) ? sh[t - off] : 0;
        __syncthreads();
        sh[t] += a;
        __syncthreads();
    }
    if (t < SNB) g_boff[t] = sh[t] - v;
}
__global__ __launch_bounds__(256) void k_scan3() {
    __shared__ int sh[256];
    int b = blockIdx.x, t = threadIdx.x;
    int base = b * SCHUNK + t * 4;
    int local[4];
    int s = 0;
#pragma unroll
    for (int i = 0; i < 4; i++) {
        int idx = base + i;
        local[i] = (idx < N_NODES) ? g_deg[idx] : 0;
        s += local[i];
    }
    sh[t] = s;
    __syncthreads();
    for (int off = 1; off < 256; off <<= 1) {
        int a = (t >= off) ? sh[t - off] : 0;
        __syncthreads();
        sh[t] += a;
        __syncthreads();
    }
    int run = g_boff[b] + sh[t] - s;
#pragma unroll
    for (int i = 0; i < 4; i++) {
        int idx = base + i;
        if (idx < N_NODES) {
            g_rowptr[idx] = run;
            g_cursor[idx] = run;
            int d = local[i];
            g_inv[idx] = 1.0f / (float)(d > 0 ? d : 1);
            run += d;
        }
    }
    if (b == 0 && t == 0) g_rowptr[N_NODES] = N_EDGES;
}
__global__ void k_scatter(const int* __restrict__ ei) {
    int i = blockIdx.x * blockDim.x + threadIdx.x;
    if (i < N_EDGES / 4) {
        int4 s4 = *(const int4*)(ei + i * 4);
        int4 d4 = *(const int4*)(ei + N_EDGES + i * 4);
        int p;
        p = atomicAdd(&g_cursor[clampN(d4.x)], 1); g_col[p] = clampN(s4.x);
        p = atomicAdd(&g_cursor[clampN(d4.y)], 1); g_col[p] = clampN(s4.y);
        p = atomicAdd(&g_cursor[clampN(d4.z)], 1); g_col[p] = clampN(s4.z);
        p = atomicAdd(&g_cursor[clampN(d4.w)], 1); g_col[p] = clampN(s4.w);
    }
}

// -------- W prep: padded bf16 hi/lo images of B[n][k] = [Wl|Wr](k, n) -------
template <int K>
__global__ void k_prepW(const float* __restrict__ Wl, const float* __restrict__ Wr) {
    constexpr int Kp = K + 8;
    int p = blockIdx.x * blockDim.x + threadIdx.x;    // pair index
    if (p >= 128 * (K / 2)) return;
    int n = p / (K / 2);
    int k = (p % (K / 2)) * 2;
    const float* W = (n < 64) ? Wl : Wr;
    int c = (n < 64) ? n : n - 64;
    float v0 = W[(size_t)k * 64 + c];
    float v1 = W[(size_t)(k + 1) * 64 + c];
    __nv_bfloat16 h0 = __float2bfloat16(v0);
    __nv_bfloat16 h1 = __float2bfloat16(v1);
    __nv_bfloat16 l0 = __float2bfloat16(v0 - __bfloat162float(h0));
    __nv_bfloat16 l1 = __float2bfloat16(v1 - __bfloat162float(h1));
    uint32_t off = (uint32_t)n * Kp + k;              // element offset, even
    __nv_bfloat162 hh; hh.x = h0; hh.y = h1;
    __nv_bfloat162 ll; ll.x = l0; ll.y = l1;
    *(__nv_bfloat162*)(g_Bhi + off * 2) = hh;
    *(__nv_bfloat162*)(g_Blo + off * 2) = ll;
}

// -------- mma.sync merged GEMM ---------------------------------------------
// CTA: 128 rows x 128 cols (A cols 0-63 -> OA, H cols 64-127 -> OH + bias).
// 8 warps, warp = 16 rows x 128 cols. bf16 split-3 in fp32 accumulators.
// smem layout: [Ahi | Alo | Bhi | Blo | bias], each part PART bytes.
template <int K>
__global__ __launch_bounds__(256) void k_gemm_mma(const float* __restrict__ Xext,
                                                  int xsel,
                                                  const float* __restrict__ bias,
                                                  int oselA, int oselH) {
    constexpr int Kp = K + 8;
    constexpr int PART = 128 * Kp * 2;      // bytes per bf16 image
    extern __shared__ __align__(16) char smem[];
    __nv_bfloat16* Ahi = (__nv_bfloat16*)smem;
    __nv_bfloat16* Alo = Ahi + 128 * Kp;
    __nv_bfloat16* Bhi = Alo + 128 * Kp;
    __nv_bfloat16* Blo = Bhi + 128 * Kp;
    float* sbias = (float*)(smem + 4 * PART);

    const float* __restrict__ X = (xsel < 0) ? Xext : getbuf(xsel);
    float* __restrict__ OA = getbuf(oselA);
    float* __restrict__ OH = getbuf(oselH);

    const int tid  = threadIdx.x;
    const int wid  = tid >> 5;
    const int lane = tid & 31;
    const int row0 = blockIdx.x * 128;

    // copy W images (global, L2-resident) -> smem
    {
        const uint4* sH = (const uint4*)g_Bhi;
        const uint4* sL = (const uint4*)g_Blo;
        uint4* dH = (uint4*)Bhi;
        uint4* dL = (uint4*)Blo;
        for (int i = tid; i < PART / 16; i += 256) { dH[i] = sH[i]; dL[i] = sL[i]; }
    }
    if (tid < 64) sbias[tid] = bias[tid];

    // load X tile, split hi/lo bf16
    for (int i = tid; i < 128 * (K / 4); i += 256) {
        int row = i / (K / 4);
        int kq  = (i % (K / 4)) * 4;
        int rr = row0 + row;
        if (rr >= N_NODES) rr = N_NODES - 1;
        float4 v = *(const float4*)(X + (size_t)rr * K + kq);
        __nv_bfloat16 h0 = __float2bfloat16(v.x), h1 = __float2bfloat16(v.y);
        __nv_bfloat16 h2 = __float2bfloat16(v.z), h3 = __float2bfloat16(v.w);
        __nv_bfloat16 l0 = __float2bfloat16(v.x - __bfloat162float(h0));
        __nv_bfloat16 l1 = __float2bfloat16(v.y - __bfloat162float(h1));
        __nv_bfloat16 l2 = __float2bfloat16(v.z - __bfloat162float(h2));
        __nv_bfloat16 l3 = __float2bfloat16(v.w - __bfloat162float(h3));
        int off = row * Kp + kq;
        __nv_bfloat162 t;
        t.x = h0; t.y = h1; *(__nv_bfloat162*)(Ahi + off)     = t;
        t.x = h2; t.y = h3; *(__nv_bfloat162*)(Ahi + off + 2) = t;
        t.x = l0; t.y = l1; *(__nv_bfloat162*)(Alo + off)     = t;
        t.x = l2; t.y = l3; *(__nv_bfloat162*)(Alo + off + 2) = t;
    }
    __syncthreads();

    // ldmatrix lane addresses
    // A (x4): r = lane%16 (row within warp's 16), c = (lane/16)*8
    const int ar = wid * 16 + (lane & 15);
    const int ac = (lane >> 4) << 3;
    const uint32_t aHiAddr = smem_u32(Ahi + ar * Kp + ac);
    const uint32_t aLoAddr = aHiAddr + (uint32_t)PART;     // Alo = Ahi + PART
    // B (x4, two n8 tiles): n = lane%8 + (lane/16)*8, k = ((lane>>3)&1)*8
    const int bn = (lane & 7) + ((lane >> 4) << 3);
    const int bk = ((lane >> 3) & 1) << 3;
    const uint32_t bHiBase = smem_u32(Bhi + bn * Kp + bk);

    float acc[16][4];
#pragma unroll
    for (int nt = 0; nt < 16; nt++)
#pragma unroll
        for (int j = 0; j < 4; j++) acc[nt][j] = 0.f;

#pragma unroll
    for (int kc = 0; kc < K / 16; kc++) {
        uint32_t ah[4], al[4];
        LDSM4(ah, aHiAddr + kc * 32);
        LDSM4(al, aLoAddr + kc * 32);
#pragma unroll
        for (int nt = 0; nt < 16; nt += 2) {
            uint32_t bh[4], bl[4];
            uint32_t bAddr = bHiBase + (uint32_t)(nt * 8 * Kp * 2) + kc * 32;
            LDSM4(bh, bAddr);
            LDSM4(bl, bAddr + (uint32_t)PART);             // Blo = Bhi + PART (R14 bug: +2*PART)
            MMA_BF16(acc[nt],     ah, bh[0], bh[1]);
            MMA_BF16(acc[nt],     ah, bl[0], bl[1]);
            MMA_BF16(acc[nt],     al, bh[0], bh[1]);
            MMA_BF16(acc[nt + 1], ah, bh[2], bh[3]);
            MMA_BF16(acc[nt + 1], ah, bl[2], bl[3]);
            MMA_BF16(acc[nt + 1], al, bh[2], bh[3]);
        }
    }

    // epilogue: thread -> rows m0, m0+8; cols nt*8 + 2*(lane%4) + {0,1}
    const int m0 = row0 + wid * 16 + (lane >> 2);
    const int nb = (lane & 3) * 2;
#pragma unroll
    for (int nt = 0; nt < 16; nt++) {
        int n = nt * 8 + nb;
        bool isH = (n >= 64);
        float* O = isH ? OH : OA;
        int col = isH ? (n - 64) : n;
        float b0 = isH ? sbias[col]     : 0.f;
        float b1 = isH ? sbias[col + 1] : 0.f;
        if (m0 < N_NODES) {
            float2 o; o.x = acc[nt][0] + b0; o.y = acc[nt][1] + b1;
            *(float2*)(O + (size_t)m0 * 64 + col) = o;
        }
        if (m0 + 8 < N_NODES) {
            float2 o; o.x = acc[nt][2] + b0; o.y = acc[nt][3] + b1;
            *(float2*)(O + (size_t)(m0 + 8) * 64 + col) = o;
        }
    }
}

// -------- SpMM + BN statistics (R11, unchanged) ----------------------------
__global__ __launch_bounds__(256) void k_spmm_stats(int asel, int hsel) {
    const float4* __restrict__ A = (const float4*)getbuf(asel);
    float* __restrict__ H = getbuf(hsel);
    __shared__ float ssum[64], ssq[64];
    if (threadIdx.x < 64) { ssum[threadIdx.x] = 0.f; ssq[threadIdx.x] = 0.f; }
    __syncthreads();

    int node = (blockIdx.x * blockDim.x + threadIdx.x) >> 4;
    int l16  = threadIdx.x & 15;
    const unsigned gmask = 0xFFFFu << (threadIdx.x & 16);
    if (node < N_NODES) {
        int beg = g_rowptr[node];
        int end = g_rowptr[node + 1];
        float4 acc = make_float4(0.f, 0.f, 0.f, 0.f);
        for (int e0 = beg; e0 < end; e0 += 16) {
            int c = (e0 + l16 < end) ? g_col[e0 + l16] : 0;
            int n = end - e0;
            if (n > 16) n = 16;
#pragma unroll 8
            for (int i = 0; i < n; i++) {
                int s = __shfl_sync(gmask, c, i, 16);
                float4 v = A[(size_t)s * 16 + l16];
                acc.x += v.x; acc.y += v.y; acc.z += v.z; acc.w += v.w;
            }
        }
        float inv = g_inv[node];
        float4* hp = (float4*)(H + (size_t)node * 64) + l16;
        float4 h = *hp;
        h.x = fmaf(acc.x, inv, h.x);
        h.y = fmaf(acc.y, inv, h.y);
        h.z = fmaf(acc.z, inv, h.z);
        h.w = fmaf(acc.w, inv, h.w);
        *hp = h;
        atomicAdd(&ssum[l16 * 4 + 0], h.x);
        atomicAdd(&ssum[l16 * 4 + 1], h.y);
        atomicAdd(&ssum[l16 * 4 + 2], h.z);
        atomicAdd(&ssum[l16 * 4 + 3], h.w);
        atomicAdd(&ssq[l16 * 4 + 0], h.x * h.x);
        atomicAdd(&ssq[l16 * 4 + 1], h.y * h.y);
        atomicAdd(&ssq[l16 * 4 + 2], h.z * h.z);
        atomicAdd(&ssq[l16 * 4 + 3], h.w * h.w);
    }
    __syncthreads();
    if (threadIdx.x < 64) {
        atomicAdd(&g_sum[threadIdx.x],   ssum[threadIdx.x]);
        atomicAdd(&g_sumsq[threadIdx.x], ssq[threadIdx.x]);
    }
}

__global__ void k_finalize(const float* __restrict__ g, const float* __restrict__ be) {
    int c = threadIdx.x;
    if (c < 64) {
        float mu  = g_sum[c] / (float)N_NODES;
        float var = g_sumsq[c] / (float)N_NODES - mu * mu;
        float sc  = g[c] * rsqrtf(var + 1e-5f);
        g_scale[c] = sc;
        g_shift[c] = be[c] - mu * sc;
        g_sum[c]   = 0.f;
        g_sumsq[c] = 0.f;
    }
}

__global__ __launch_bounds__(256) void k_bnrelu(int hsel) {
    float* __restrict__ H = getbuf(hsel);
    int i = blockIdx.x * blockDim.x + threadIdx.x;
    if (i < N_NODES * 16) {
        float4 v = ((float4*)H)[i];
        int c = (i & 15) * 4;
        v.x = fmaxf(fmaf(v.x, g_scale[c + 0], g_shift[c + 0]), 0.f);
        v.y = fmaxf(fmaf(v.y, g_scale[c + 1], g_shift[c + 1]), 0.f);
        v.z = fmaxf(fmaf(v.z, g_scale[c + 2], g_shift[c + 2]), 0.f);
        v.w = fmaxf(fmaf(v.w, g_scale[c + 3], g_shift[c + 3]), 0.f);
        ((float4*)H)[i] = v;
    }
}

// -------- fusion MLP (applies layer-3 BN+ReLU on the fly) -------------------
__global__ __launch_bounds__(256) void k_fusion(int hsel,
                                                const float* __restrict__ xgb,
                                                const float* __restrict__ Wf1,
                                                const float* __restrict__ bf1,
                                                const float* __restrict__ Wf2,
                                                const float* __restrict__ bf2,
                                                float* __restrict__ out) {
    const float* __restrict__ H = getbuf(hsel);
    __shared__ float sW[65 * 64];
    __shared__ float sb1[64], sW2[64], ssc[64], ssh[64];
    __shared__ float sb2;
    for (int i = threadIdx.x; i < 65 * 64; i += 256) sW[i] = Wf1[i];
    if (threadIdx.x < 64) {
        sb1[threadIdx.x] = bf1[threadIdx.x];
        sW2[threadIdx.x] = Wf2[threadIdx.x];
        ssc[threadIdx.x] = g_scale[threadIdx.x];
        ssh[threadIdx.x] = g_shift[threadIdx.x];
    }
    if (threadIdx.x == 0) sb2 = bf2[0];
    __syncthreads();

    int node = blockIdx.x * 256 + threadIdx.x;
    if (node >= N_NODES) return;

    const float4* hp = (const float4*)(H + (size_t)node * 64);
    float4 acc[16];
#pragma unroll
    for (int jg = 0; jg < 16; jg++) acc[jg] = ((const float4*)sb1)[jg];

    for (int kc = 0; kc < 8; kc++) {
        float  hv[8];
        float4 h0 = hp[kc * 2];
        float4 h1 = hp[kc * 2 + 1];
        hv[0] = h0.x; hv[1] = h0.y; hv[2] = h0.z; hv[3] = h0.w;
        hv[4] = h1.x; hv[5] = h1.y; hv[6] = h1.z; hv[7] = h1.w;
#pragma unroll
        for (int kk = 0; kk < 8; kk++) {
            int ch = kc * 8 + kk;
            float x = fmaxf(fmaf(hv[kk], ssc[ch], ssh[ch]), 0.f);
            const float* wr = &sW[ch * 64];
#pragma unroll
            for (int jg = 0; jg < 16; jg++) {
                float4 w = *(const float4*)&wr[jg * 4];
                acc[jg].x = fmaf(x, w.x, acc[jg].x);
                acc[jg].y = fmaf(x, w.y, acc[jg].y);
                acc[jg].z = fmaf(x, w.z, acc[jg].z);
                acc[jg].w = fmaf(x, w.w, acc[jg].w);
            }
        }
    }

    float xg    = xgb[node];
    float logit = sb2;
#pragma unroll
    for (int jg = 0; jg < 16; jg++) {
        float4 w = *(const float4*)&sW[64 * 64 + jg * 4];
        float4 a = acc[jg];
        a.x = fmaxf(fmaf(xg, w.x, a.x), 0.f);
        a.y = fmaxf(fmaf(xg, w.y, a.y), 0.f);
        a.z = fmaxf(fmaf(xg, w.z, a.z), 0.f);
        a.w = fmaxf(fmaf(xg, w.w, a.w), 0.f);
        float4 v2 = *(const float4*)&sW2[jg * 4];
        logit += a.x * v2.x + a.y * v2.y + a.z * v2.z + a.w * v2.w;
    }
    out[node] = logit;
}

// ---------------------------------------------------------------------------
extern "C" void kernel_launch(void* const* d_in, const int* in_sizes, int n_in,
                              void* d_out, int out_size) {
    const float* x    = (const float*)d_in[0];
    const int*   ei   = (const int*)d_in[1];
    const float* xgb  = (const float*)d_in[2];
    const float* W1l  = (const float*)d_in[3];
    const float* b1   = (const float*)d_in[4];
    const float* W1r  = (const float*)d_in[5];
    const float* g1   = (const float*)d_in[6];
    const float* be1  = (const float*)d_in[7];
    const float* W2l  = (const float*)d_in[8];
    const float* b2   = (const float*)d_in[9];
    const float* W2r  = (const float*)d_in[10];
    const float* g2   = (const float*)d_in[11];
    const float* be2  = (const float*)d_in[12];
    const float* W3l  = (const float*)d_in[13];
    const float* b3   = (const float*)d_in[14];
    const float* W3r  = (const float*)d_in[15];
    const float* g3   = (const float*)d_in[16];
    const float* be3  = (const float*)d_in[17];
    const float* Wf1  = (const float*)d_in[18];
    const float* bf1  = (const float*)d_in[19];
    const float* Wf2  = (const float*)d_in[20];
    const float* bf2  = (const float*)d_in[21];
    float*       out  = (float*)d_out;

    const int E4B = (N_EDGES / 4 + 255) / 256;
    const int GB  = (N_NODES + 127) / 128;
    const int SB  = (N_NODES * 16 + 255) / 256;
    const int VB  = (N_NODES * 16 + 255) / 256;
    const int FB  = (N_NODES + 255) / 256;

    const int SMEM128 = 4 * (128 * 136 * 2) + 256;   // 139520
    const int SMEM64  = 4 * (128 * 72 * 2) + 256;    // 73984
    cudaFuncSetAttribute(k_gemm_mma<128>, cudaFuncAttributeMaxDynamicSharedMemorySize, SMEM128);
    cudaFuncSetAttribute(k_gemm_mma<64>,  cudaFuncAttributeMaxDynamicSharedMemorySize, SMEM64);

    // CSR hist + layer-1 W prep
    k_zero_deg<<<(N_NODES + 255) / 256, 256>>>();
    k_hist<<<E4B, 256>>>(ei);
    k_prepW<128><<<(128 * 64 + 255) / 256, 256>>>(W1l, W1r);

    // 4th launch (profiled slot): layer-1 mma GEMM
    k_gemm_mma<128><<<GB, 256, SMEM128>>>(x, -1, b1, 0, 2);

    // finish CSR
    k_scan1<<<SNB, 256>>>();
    k_scan2<<<1, 128>>>();
    k_scan3<<<SNB, 256>>>();
    k_scatter<<<E4B, 256>>>(ei);
    k_zero_stats<<<1, 64>>>();

    // layer 1 aggregate + BN (in-place)
    k_spmm_stats<<<SB, 256>>>(0, 2);
    k_finalize<<<1, 64>>>(g1, be1);
    k_bnrelu<<<VB, 256>>>(2);

    // layer 2
    k_prepW<64><<<(128 * 32 + 255) / 256, 256>>>(W2l, W2r);
    k_gemm_mma<64><<<GB, 256, SMEM64>>>(nullptr, 2, b2, 0, 1);
    k_spmm_stats<<<SB, 256>>>(0, 1);
    k_finalize<<<1, 64>>>(g2, be2);
    k_bnrelu<<<VB, 256>>>(1);

    // layer 3 (BN3 applied inside fusion)
    k_prepW<64><<<(128 * 32 + 255) / 256, 256>>>(W3l, W3r);
    k_gemm_mma<64><<<GB, 256, SMEM64>>>(nullptr, 1, b3, 0, 2);
    k_spmm_stats<<<SB, 256>>>(0, 2);
    k_finalize<<<1, 64>>>(g3, be3);

    // fusion
    k_fusion<<<FB, 256>>>(2, xgb, Wf1, bf1, Wf2, bf2, out);
}